// round 3
// baseline (speedup 1.0000x reference)
#include <cuda_runtime.h>
#include <cuda_bf16.h>
#include <stdint.h>

// Problem constants (fixed by the reference)
constexpr int NU = 100000;
constexpr int NI = 50000;
constexpr int NN = NU + NI;          // 150000 nodes
constexpr int D  = 64;               // embedding dim
constexpr int D2 = D / 2;            // float2 per row
constexpr int MAX_E = 4800000;       // 2 * E_HALF
constexpr int NLAYERS = 3;

constexpr int SCAN_CHUNK = 1024;
constexpr int SCAN_NB = (NN + SCAN_CHUNK - 1) / SCAN_CHUNK;  // 147

// ---- device scratch (static; no runtime allocation allowed) ----
__device__ float g_xbuf[2][(size_t)NN * D];   // ping-pong feature buffers (76.8 MB)
__device__ int   g_col[MAX_E];
__device__ float g_w[MAX_E];
__device__ int   g_deg[NN];
__device__ int   g_rowstart[NN + 1];
__device__ int   g_cursor[NN];
__device__ float g_dinv[NN];
__device__ int   g_part[SCAN_NB];
__device__ int   g_partoff[SCAN_NB];

// ---------------------------------------------------------------
__global__ void zero_deg_kernel() {
    int i = blockIdx.x * blockDim.x + threadIdx.x;
    if (i < NN) g_deg[i] = 0;
}

__global__ void hist_kernel(const int* __restrict__ dst, int E) {
    int i = blockIdx.x * blockDim.x + threadIdx.x;
    int stride = gridDim.x * blockDim.x;
    for (; i < E; i += stride) {
        int d = dst[i];
        if (d >= 0 && d < NN) atomicAdd(&g_deg[d], 1);
    }
}

// scan phase 1: per-block partial sums of deg
__global__ void scan1_kernel() {
    __shared__ int sh[SCAN_CHUNK];
    int t = threadIdx.x;
    int i = blockIdx.x * SCAN_CHUNK + t;
    sh[t] = (i < NN) ? g_deg[i] : 0;
    __syncthreads();
    for (int off = SCAN_CHUNK / 2; off > 0; off >>= 1) {
        if (t < off) sh[t] += sh[t + off];
        __syncthreads();
    }
    if (t == 0) g_part[blockIdx.x] = sh[0];
}

// scan phase 2: exclusive scan of partials (single thread; 147 elems)
__global__ void scan2_kernel() {
    if (threadIdx.x == 0 && blockIdx.x == 0) {
        int run = 0;
        for (int b = 0; b < SCAN_NB; b++) {
            int v = g_part[b];
            g_partoff[b] = run;
            run += v;
        }
        g_rowstart[NN] = run;  // == E
    }
}

// scan phase 3: per-block exclusive scan + offset -> rowstart, cursor
__global__ void scan3_kernel() {
    __shared__ int sh[SCAN_CHUNK];
    int t = threadIdx.x;
    int i = blockIdx.x * SCAN_CHUNK + t;
    int v = (i < NN) ? g_deg[i] : 0;
    sh[t] = v;
    __syncthreads();
    // Hillis-Steele inclusive scan
    for (int off = 1; off < SCAN_CHUNK; off <<= 1) {
        int x = (t >= off) ? sh[t - off] : 0;
        __syncthreads();
        sh[t] += x;
        __syncthreads();
    }
    if (i < NN) {
        int excl = sh[t] - v + g_partoff[blockIdx.x];
        g_rowstart[i] = excl;
        g_cursor[i]   = excl;
    }
}

__global__ void dinv_kernel() {
    int i = blockIdx.x * blockDim.x + threadIdx.x;
    if (i < NN) {
        int d = g_deg[i];
        g_dinv[i] = (d > 0) ? rsqrtf((float)d) : 0.0f;
    }
}

__global__ void scatter_kernel(const int* __restrict__ src,
                               const int* __restrict__ dst, int E) {
    int i = blockIdx.x * blockDim.x + threadIdx.x;
    int stride = gridDim.x * blockDim.x;
    for (; i < E; i += stride) {
        int s = src[i];
        int d = dst[i];
        if (s < 0 || s >= NN || d < 0 || d >= NN) continue;
        int pos = atomicAdd(&g_cursor[d], 1);
        g_col[pos] = s;
        g_w[pos]   = g_dinv[s] * g_dinv[d];
    }
}

// init: x0 = concat(user_emb, item_emb); out = 0.25 * x0
__global__ void init_kernel(const float* __restrict__ user_emb,
                            const float* __restrict__ item_emb,
                            float* __restrict__ out) {
    int i = blockIdx.x * blockDim.x + threadIdx.x;
    int total = NN * D;
    int stride = gridDim.x * blockDim.x;
    for (; i < total; i += stride) {
        float v = (i < NU * D) ? user_emb[i] : item_emb[i - NU * D];
        g_xbuf[0][i] = v;
        out[i] = 0.25f * v;
    }
}

// SpMM layer: x_out[row] = sum_e w[e] * x_in[col[e]];  out += 0.25 * x_out
// warp per row, lane owns one float2 (8B) of the 256B row.
__global__ void spmm_kernel(int inbuf, float* __restrict__ out) {
    const float2* __restrict__ xin = (const float2*)g_xbuf[inbuf];
    float2* __restrict__ xout = (float2*)g_xbuf[1 - inbuf];
    float2* __restrict__ outp = (float2*)out;

    int warp_id = (blockIdx.x * blockDim.x + threadIdx.x) >> 5;
    if (warp_id >= NN) return;
    int lane = threadIdx.x & 31;
    int row = warp_id;

    int s = g_rowstart[row];
    int e = g_rowstart[row + 1];

    float2 acc = make_float2(0.0f, 0.0f);

    int k = s;
    for (; k + 4 <= e; k += 4) {
        int   c0 = g_col[k],   c1 = g_col[k+1], c2 = g_col[k+2], c3 = g_col[k+3];
        float w0 = g_w[k],     w1 = g_w[k+1],   w2 = g_w[k+2],   w3 = g_w[k+3];
        float2 v0 = xin[(size_t)c0 * D2 + lane];
        float2 v1 = xin[(size_t)c1 * D2 + lane];
        float2 v2 = xin[(size_t)c2 * D2 + lane];
        float2 v3 = xin[(size_t)c3 * D2 + lane];
        acc.x = fmaf(w0, v0.x, acc.x); acc.y = fmaf(w0, v0.y, acc.y);
        acc.x = fmaf(w1, v1.x, acc.x); acc.y = fmaf(w1, v1.y, acc.y);
        acc.x = fmaf(w2, v2.x, acc.x); acc.y = fmaf(w2, v2.y, acc.y);
        acc.x = fmaf(w3, v3.x, acc.x); acc.y = fmaf(w3, v3.y, acc.y);
    }
    for (; k < e; k++) {
        int c = g_col[k];
        float wgt = g_w[k];
        float2 v = xin[(size_t)c * D2 + lane];
        acc.x = fmaf(wgt, v.x, acc.x);
        acc.y = fmaf(wgt, v.y, acc.y);
    }

    size_t off = (size_t)row * D2 + lane;
    xout[off] = acc;
    float2 o = outp[off];
    o.x = fmaf(0.25f, acc.x, o.x);
    o.y = fmaf(0.25f, acc.y, o.y);
    outp[off] = o;
}

// ---------------------------------------------------------------
extern "C" void kernel_launch(void* const* d_in, const int* in_sizes, int n_in,
                              void* d_out, int out_size) {
    const float* user_emb = (const float*)d_in[0];
    const float* item_emb = (const float*)d_in[1];
    const int* edge_index = (const int*)d_in[2];   // int64 in reference -> int32 on device
    float* out = (float*)d_out;

    int E = in_sizes[2] / 2;  // edge_index is [2, E]
    if (E > MAX_E) E = MAX_E;
    const int* src = edge_index;
    const int* dst = edge_index + E;

    // 1. degree histogram
    zero_deg_kernel<<<(NN + 255) / 256, 256>>>();
    {
        int blocks = (E + 255) / 256;
        if (blocks > 8192) blocks = 8192;
        hist_kernel<<<blocks, 256>>>(dst, E);
    }

    // 2. exclusive scan -> rowstart, cursor
    scan1_kernel<<<SCAN_NB, SCAN_CHUNK>>>();
    scan2_kernel<<<1, 32>>>();
    scan3_kernel<<<SCAN_NB, SCAN_CHUNK>>>();

    // 3. dinv
    dinv_kernel<<<(NN + 255) / 256, 256>>>();

    // 4. scatter edges into CSR (col + precomputed weight)
    {
        int blocks = (E + 255) / 256;
        if (blocks > 8192) blocks = 8192;
        scatter_kernel<<<blocks, 256>>>(src, dst, E);
    }

    // 5. init x0 and out accumulator
    init_kernel<<<2048, 256>>>(user_emb, item_emb, out);

    // 6. three SpMM layers (warp per row, 8 warps/block)
    int spmm_blocks = (NN * 32 + 255) / 256;
    int cur = 0;
    for (int l = 0; l < NLAYERS; l++) {
        spmm_kernel<<<spmm_blocks, 256>>>(cur, out);
        cur = 1 - cur;
    }
}

// round 8
// speedup vs baseline: 1.3514x; 1.3514x over previous
#include <cuda_runtime.h>
#include <cuda_fp16.h>
#include <stdint.h>

// Problem constants (fixed by the reference)
constexpr int NU = 100000;
constexpr int NI = 50000;
constexpr int NN = NU + NI;          // 150000 nodes
constexpr int D  = 64;               // embedding dim
constexpr int DH = D / 2;            // half2 / float2 per row = 32
constexpr int MAX_E = 4800000;       // 2 * E_HALF
constexpr int NLAYERS = 3;

constexpr int SCAN_CHUNK = 1024;
constexpr int SCAN_NB = (NN + SCAN_CHUNK - 1) / SCAN_CHUNK;  // 147

// ---- device scratch (static; no runtime allocation allowed) ----
// y buffers hold dinv-prescaled features in fp16 (half2 packed in uint32).
__device__ unsigned int g_y[2][(size_t)NN * DH];   // 19.2 MB each
__device__ int   g_col[MAX_E];
__device__ int   g_deg[NN];
__device__ int   g_rowstart[NN + 1];
__device__ int   g_cursor[NN];
__device__ float g_dinv[NN];
__device__ int   g_part[SCAN_NB];
__device__ int   g_partoff[SCAN_NB];

// ---------------------------------------------------------------
__global__ void zero_deg_kernel() {
    int i = blockIdx.x * blockDim.x + threadIdx.x;
    if (i < NN) g_deg[i] = 0;
}

__global__ void hist_kernel(const int* __restrict__ dst, int E) {
    int i = blockIdx.x * blockDim.x + threadIdx.x;
    int stride = gridDim.x * blockDim.x;
    for (; i < E; i += stride) {
        int d = dst[i];
        if (d >= 0 && d < NN) atomicAdd(&g_deg[d], 1);
    }
}

// scan phase 1: per-block partial sums of deg
__global__ void scan1_kernel() {
    __shared__ int sh[SCAN_CHUNK];
    int t = threadIdx.x;
    int i = blockIdx.x * SCAN_CHUNK + t;
    sh[t] = (i < NN) ? g_deg[i] : 0;
    __syncthreads();
    for (int off = SCAN_CHUNK / 2; off > 0; off >>= 1) {
        if (t < off) sh[t] += sh[t + off];
        __syncthreads();
    }
    if (t == 0) g_part[blockIdx.x] = sh[0];
}

// scan phase 2: exclusive scan of partials (single thread; 147 elems)
__global__ void scan2_kernel() {
    if (threadIdx.x == 0 && blockIdx.x == 0) {
        int run = 0;
        for (int b = 0; b < SCAN_NB; b++) {
            int v = g_part[b];
            g_partoff[b] = run;
            run += v;
        }
        g_rowstart[NN] = run;  // == E
    }
}

// scan phase 3: per-block exclusive scan + offset -> rowstart, cursor, dinv
__global__ void scan3_kernel() {
    __shared__ int sh[SCAN_CHUNK];
    int t = threadIdx.x;
    int i = blockIdx.x * SCAN_CHUNK + t;
    int v = (i < NN) ? g_deg[i] : 0;
    sh[t] = v;
    __syncthreads();
    // Hillis-Steele inclusive scan
    for (int off = 1; off < SCAN_CHUNK; off <<= 1) {
        int x = (t >= off) ? sh[t - off] : 0;
        __syncthreads();
        sh[t] += x;
        __syncthreads();
    }
    if (i < NN) {
        int excl = sh[t] - v + g_partoff[blockIdx.x];
        g_rowstart[i] = excl;
        g_cursor[i]   = excl;
        g_dinv[i]     = (v > 0) ? rsqrtf((float)v) : 0.0f;
    }
}

__global__ void scatter_kernel(const int* __restrict__ src,
                               const int* __restrict__ dst, int E) {
    int i = blockIdx.x * blockDim.x + threadIdx.x;
    int stride = gridDim.x * blockDim.x;
    for (; i < E; i += stride) {
        int s = src[i];
        int d = dst[i];
        if (s < 0 || s >= NN || d < 0 || d >= NN) continue;
        int pos = atomicAdd(&g_cursor[d], 1);
        g_col[pos] = s;
    }
}

// init: x0 = concat(user_emb, item_emb)
//   out = 0.25 * x0   (fp32)
//   y0  = dinv * x0   (fp16, prescaled)
__global__ void init_kernel(const float* __restrict__ user_emb,
                            const float* __restrict__ item_emb,
                            float* __restrict__ out) {
    __half2* __restrict__ y0 = reinterpret_cast<__half2*>(g_y[0]);
    float2* __restrict__ outp = (float2*)out;
    int i = blockIdx.x * blockDim.x + threadIdx.x;
    int total = NN * DH;          // half2/float2 granularity
    int stride = gridDim.x * blockDim.x;
    for (; i < total; i += stride) {
        int f = i * 2;            // float element index into concat(x)
        float v0, v1;
        if (f < NU * D) {
            v0 = user_emb[f];
            v1 = user_emb[f + 1];
        } else {
            v0 = item_emb[f - NU * D];
            v1 = item_emb[f - NU * D + 1];
        }
        float di = g_dinv[i / DH];
        outp[i] = make_float2(0.25f * v0, 0.25f * v1);
        y0[i] = __floats2half2_rn(di * v0, di * v1);
    }
}

// SpMM layer on prescaled features:
//   sum[d]   = sum_{s in N(d)} y_in[s]          (pure adds, fp32 acc)
//   x_l[d]   = dinv[d] * sum[d]
//   out[d]  += 0.25 * x_l[d]                    (fp32)
//   y_out[d] = dinv[d] * x_l[d] = dinv[d]^2*sum (fp16)
// warp per row; lane owns one half2 (4B) of the 128B fp16 row.
__global__ void spmm_kernel(int inbuf, float* __restrict__ out) {
    const __half2* __restrict__ yin = reinterpret_cast<const __half2*>(g_y[inbuf]);
    __half2* __restrict__ yout = reinterpret_cast<__half2*>(g_y[1 - inbuf]);
    float2* __restrict__ outp = (float2*)out;

    int warp_id = (blockIdx.x * blockDim.x + threadIdx.x) >> 5;
    if (warp_id >= NN) return;
    int lane = threadIdx.x & 31;
    int row = warp_id;

    int s = g_rowstart[row];
    int e = g_rowstart[row + 1];

    float2 acc = make_float2(0.0f, 0.0f);

    int k = s;
    for (; k + 8 <= e; k += 8) {
        int c0 = g_col[k],   c1 = g_col[k+1], c2 = g_col[k+2], c3 = g_col[k+3];
        int c4 = g_col[k+4], c5 = g_col[k+5], c6 = g_col[k+6], c7 = g_col[k+7];
        float2 v0 = __half22float2(yin[c0 * DH + lane]);
        float2 v1 = __half22float2(yin[c1 * DH + lane]);
        float2 v2 = __half22float2(yin[c2 * DH + lane]);
        float2 v3 = __half22float2(yin[c3 * DH + lane]);
        float2 v4 = __half22float2(yin[c4 * DH + lane]);
        float2 v5 = __half22float2(yin[c5 * DH + lane]);
        float2 v6 = __half22float2(yin[c6 * DH + lane]);
        float2 v7 = __half22float2(yin[c7 * DH + lane]);
        acc.x += (v0.x + v1.x) + (v2.x + v3.x) + ((v4.x + v5.x) + (v6.x + v7.x));
        acc.y += (v0.y + v1.y) + (v2.y + v3.y) + ((v4.y + v5.y) + (v6.y + v7.y));
    }
    for (; k < e; k++) {
        float2 v = __half22float2(yin[g_col[k] * DH + lane]);
        acc.x += v.x;
        acc.y += v.y;
    }

    float di = g_dinv[row];
    float xlx = di * acc.x;
    float xly = di * acc.y;

    size_t off = (size_t)row * DH + lane;
    float2 o = outp[off];
    o.x = fmaf(0.25f, xlx, o.x);
    o.y = fmaf(0.25f, xly, o.y);
    outp[off] = o;
    yout[off] = __floats2half2_rn(di * xlx, di * xly);
}

// ---------------------------------------------------------------
extern "C" void kernel_launch(void* const* d_in, const int* in_sizes, int n_in,
                              void* d_out, int out_size) {
    const float* user_emb = (const float*)d_in[0];
    const float* item_emb = (const float*)d_in[1];
    const int* edge_index = (const int*)d_in[2];   // int64 in reference -> int32 on device
    float* out = (float*)d_out;

    int E = in_sizes[2] / 2;  // edge_index is [2, E]
    if (E > MAX_E) E = MAX_E;
    const int* src = edge_index;
    const int* dst = edge_index + E;

    // 1. degree histogram
    zero_deg_kernel<<<(NN + 255) / 256, 256>>>();
    {
        int blocks = (E + 255) / 256;
        if (blocks > 8192) blocks = 8192;
        hist_kernel<<<blocks, 256>>>(dst, E);
    }

    // 2. exclusive scan -> rowstart, cursor (+dinv fused)
    scan1_kernel<<<SCAN_NB, SCAN_CHUNK>>>();
    scan2_kernel<<<1, 32>>>();
    scan3_kernel<<<SCAN_NB, SCAN_CHUNK>>>();

    // 3. scatter edges into CSR (col only; weights factored into dinv scaling)
    {
        int blocks = (E + 255) / 256;
        if (blocks > 8192) blocks = 8192;
        scatter_kernel<<<blocks, 256>>>(src, dst, E);
    }

    // 4. init y0 (prescaled fp16) and out accumulator
    init_kernel<<<2048, 256>>>(user_emb, item_emb, out);

    // 5. three SpMM layers (warp per row, 8 warps/block)
    int spmm_blocks = (NN * 32 + 255) / 256;
    int cur = 0;
    for (int l = 0; l < NLAYERS; l++) {
        spmm_kernel<<<spmm_blocks, 256>>>(cur, out);
        cur = 1 - cur;
    }
}